// round 14
// baseline (speedup 1.0000x reference)
#include <cuda_runtime.h>
#include <cstdint>

// Shapes (fixed):
//   x_main: [1, T=128, M=512, K=256] fp32
//   x_aux : [K=256, T=128, Da=256]   fp32
//   W     : [Da=256, E=512]          fp32
//   b     : [E=512]                  fp32
//   out   : [1,T,M,E,1] = [128,512,512] fp32
//
// Base: R11 (168.7us, rel_err 5.49e-4).  R13's stage-1 RZ truncation REVERTED
// (margin not worth noise-level gain).  Stage 2 re-tiled to CTA 256x128 with
// 512 threads (16 warps, 4m x 4n, warp tile 64x32 unchanged): ~7% less
// crossbar traffic per tensor-cycle and half the barriers per MAC, at the
// cost of 1 CTA/SM (warps/SM unchanged at 16).
//
// Stage 1 (per t): scratch[t][e][k] = relu( sum_d Wt[e][d]*x_aux[k][t][d] + b[e] )
//   A = Wt rows e (cp.async, RN tf32), B = x_aux rows k (LDG + cvt.rna + STS).
// Stage 2 (per t): out[t][m][e] = sum_k x_main[t][m][k]*scratch[t][e][k]
//   A = raw fp32 x_main (HW RZ-truncated by MMA), B = scratch (RN tf32),
//   both cp.async.

__device__ __align__(16) float g_scratch[128 * 512 * 256];  // [T][E][K], 64 MB
__device__ __align__(16) float g_Wt[512 * 256];             // W^T, tf32-rounded

static constexpr int S_A = 18432;        // stage1: 128 rows x 144 B
static constexpr int S_B = 18432;
static constexpr int SMEM_S1 = 2 * (S_A + S_B);            // 73728, 2 CTAs/SM

static constexpr int S2_A = 36864;       // stage2: 256 rows x 144 B
static constexpr int S2_B = 18432;       // 128 rows x 144 B
static constexpr int S2_STAGE = S2_A + S2_B;               // 55296
static constexpr int SMEM_S2 = 2 * S2_STAGE;               // 110592, 1 CTA/SM

__device__ __forceinline__ uint32_t smem_u32(const void* p) {
    uint32_t a;
    asm("{ .reg .u64 t; cvta.to.shared.u64 t, %1; cvt.u32.u64 %0, t; }" : "=r"(a) : "l"(p));
    return a;
}
__device__ __forceinline__ float f2tf32f(float f) {
    uint32_t r;
    asm("cvt.rna.tf32.f32 %0, %1;" : "=r"(r) : "f"(f));
    return __uint_as_float(r);
}
#define CP_ASYNC16(dst32, src) \
    asm volatile("cp.async.cg.shared.global [%0], [%1], 16;" :: "r"(dst32), "l"(src))
#define CP_COMMIT() asm volatile("cp.async.commit_group;" ::: "memory")
#define CP_WAIT0()  asm volatile("cp.async.wait_group 0;" ::: "memory")
#define CP_WAIT1()  asm volatile("cp.async.wait_group 1;" ::: "memory")
#define STS128(addr, v) \
    asm volatile("st.shared.v4.b32 [%0], {%1,%2,%3,%4};" \
                 :: "r"(addr), "f"(v.x), "f"(v.y), "f"(v.z), "f"(v.w) : "memory")
#define LDSM4(r0, r1, r2, r3, addr) \
    asm volatile("ldmatrix.sync.aligned.m8n8.x4.shared.b16 {%0,%1,%2,%3}, [%4];" \
                 : "=r"(r0), "=r"(r1), "=r"(r2), "=r"(r3) : "r"(addr))

__device__ __forceinline__ void mma_tf32(float* d, uint32_t a0, uint32_t a1,
                                         uint32_t a2, uint32_t a3,
                                         uint32_t b0, uint32_t b1) {
    asm volatile(
        "mma.sync.aligned.m16n8k8.row.col.f32.tf32.tf32.f32 "
        "{%0,%1,%2,%3}, {%4,%5,%6,%7}, {%8,%9}, {%0,%1,%2,%3};"
        : "+f"(d[0]), "+f"(d[1]), "+f"(d[2]), "+f"(d[3])
        : "r"(a0), "r"(a1), "r"(a2), "r"(a3), "r"(b0), "r"(b1));
}

// Pre-pass: Wt[e][d] = rna_tf32(W[d][e]).  32x32 smem-tiled transpose.
__global__ void w_transpose_kernel(const float* __restrict__ W) {
    __shared__ float s[32][33];
    const int d0 = blockIdx.x * 32, e0 = blockIdx.y * 32;
    const int tx = threadIdx.x, ty = threadIdx.y;
    s[ty][tx] = W[(size_t)(d0 + ty) * 512 + e0 + tx];
    __syncthreads();
    g_Wt[(size_t)(e0 + ty) * 256 + d0 + tx] = f2tf32f(s[tx][ty]);
}

// ============================ Stage 1 (R11 verbatim) ============================
__global__ void __launch_bounds__(256, 2)
slam_stage1(const float* __restrict__ x_aux, const float* __restrict__ bias) {
    extern __shared__ __align__(16) char smem[];
    const uint32_t sb = smem_u32(smem);
    const int tid = threadIdx.x, wid = tid >> 5, lid = tid & 31;
    const int g = lid >> 2, tg = lid & 3;
    const int warp_m = (wid & 1) * 64;
    const int warp_n = (wid >> 1) * 32;
    const int t = blockIdx.z, m0 = blockIdx.y * 128, n0 = blockIdx.x * 128;

    const float* ld_src = x_aux + (size_t)t * 256;      // rows k, stride 32768
    float* C = g_scratch + (size_t)t * 512 * 256;       // [e][k]

    const uint32_t aoff[2] = {sb, sb + S_A};
    const uint32_t boff[2] = {sb + 2 * S_A, sb + 2 * S_A + S_B};

    auto cpasync_tile = [&](int kt, int buf) {
#pragma unroll
        for (int i = 0; i < 4; ++i) {
            const int idx = tid + i * 256;
            const int row = idx >> 3, ch = idx & 7;
            CP_ASYNC16(aoff[buf] + row * 144 + ch * 16,
                       g_Wt + (size_t)(m0 + row) * 256 + kt * 32 + ch * 4);
        }
    };
    const int srow = tid >> 3, sch = tid & 7;
    auto ldg_tile = [&](int kt, float4 (&r)[4]) {
#pragma unroll
        for (int i = 0; i < 4; ++i)
            r[i] = *reinterpret_cast<const float4*>(
                ld_src + (size_t)(n0 + srow + i * 32) * (128 * 256) + kt * 32 + sch * 4);
    };
    auto sts_tile = [&](float4 (&r)[4], int buf) {
        const uint32_t base = boff[buf] + srow * 144 + sch * 16;
#pragma unroll
        for (int i = 0; i < 4; ++i) {
            float4 v = r[i];
            v.x = f2tf32f(v.x); v.y = f2tf32f(v.y);
            v.z = f2tf32f(v.z); v.w = f2tf32f(v.w);
            STS128(base + i * 32 * 144, v);
        }
    };

    const uint32_t a_lane = (uint32_t)(((((lid >> 3) & 1) * 8) + (lid & 7)) * 144
                                       + ((lid >> 4) & 1) * 16);
    const uint32_t b_lane = (uint32_t)(((((lid >> 4) & 1) * 8) + (lid & 7)) * 144
                                       + ((lid >> 3) & 1) * 16);

    float acc[4][4][4];
#pragma unroll
    for (int mi = 0; mi < 4; ++mi)
#pragma unroll
        for (int nj = 0; nj < 4; ++nj)
#pragma unroll
            for (int q = 0; q < 4; ++q) acc[mi][nj][q] = 0.0f;

    auto compute_tile = [&](int buf) {
        const uint32_t ab = aoff[buf] + a_lane + warp_m * 144;
        const uint32_t bb = boff[buf] + b_lane + warp_n * 144;
#pragma unroll
        for (int ks = 0; ks < 4; ++ks) {
            uint32_t af[4][4], bf[4][2];
#pragma unroll
            for (int mi = 0; mi < 4; ++mi)
                LDSM4(af[mi][0], af[mi][1], af[mi][2], af[mi][3],
                      ab + mi * (16 * 144) + ks * 32);
#pragma unroll
            for (int p = 0; p < 2; ++p)
                LDSM4(bf[2 * p][0], bf[2 * p][1], bf[2 * p + 1][0], bf[2 * p + 1][1],
                      bb + p * (16 * 144) + ks * 32);
#pragma unroll
            for (int mi = 0; mi < 4; ++mi)
#pragma unroll
                for (int nj = 0; nj < 4; ++nj)
                    mma_tf32(acc[mi][nj], af[mi][0], af[mi][1], af[mi][2], af[mi][3],
                             bf[nj][0], bf[nj][1]);
        }
    };

    float4 stage_regs[4];
    cpasync_tile(0, 0);
    CP_COMMIT();
    ldg_tile(0, stage_regs);
    CP_WAIT0();
    sts_tile(stage_regs, 0);
    __syncthreads();

    int buf = 0;
#pragma unroll 1
    for (int kt = 0; kt < 8; ++kt) {
        if (kt < 7) {
            cpasync_tile(kt + 1, buf ^ 1);
            CP_COMMIT();
            ldg_tile(kt + 1, stage_regs);
        }
        compute_tile(buf);
        if (kt < 7) {
            CP_WAIT0();
            sts_tile(stage_regs, buf ^ 1);
            __syncthreads();
        }
        buf ^= 1;
    }

#pragma unroll
    for (int mi = 0; mi < 4; ++mi) {
        const int r0 = m0 + warp_m + 16 * mi + g;
        const int r1 = r0 + 8;
        const float bv0 = bias[r0], bv1 = bias[r1];
#pragma unroll
        for (int nj = 0; nj < 4; ++nj) {
            const int col = n0 + warp_n + 8 * nj + 2 * tg;
            float2 v0, v1;
            v0.x = f2tf32f(fmaxf(acc[mi][nj][0] + bv0, 0.0f));
            v0.y = f2tf32f(fmaxf(acc[mi][nj][1] + bv0, 0.0f));
            v1.x = f2tf32f(fmaxf(acc[mi][nj][2] + bv1, 0.0f));
            v1.y = f2tf32f(fmaxf(acc[mi][nj][3] + bv1, 0.0f));
            *reinterpret_cast<float2*>(C + (size_t)r0 * 256 + col) = v0;
            *reinterpret_cast<float2*>(C + (size_t)r1 * 256 + col) = v1;
        }
    }
}

// ============ Stage 2: CTA 256x128, 512 threads (16 warps, 4m x 4n) ============
__global__ void __launch_bounds__(512, 1)
slam_stage2(const float* __restrict__ x_main, float* __restrict__ out) {
    extern __shared__ __align__(16) char smem[];
    const uint32_t sb = smem_u32(smem);
    const int tid = threadIdx.x, wid = tid >> 5, lid = tid & 31;
    const int g = lid >> 2, tg = lid & 3;
    const int warp_m = (wid & 3) * 64;     // 4 m-groups
    const int warp_n = (wid >> 2) * 32;    // 4 n-groups
    const int t = blockIdx.z, m0 = blockIdx.y * 256, n0 = blockIdx.x * 128;

    const float* A = x_main + (size_t)t * 512 * 256;       // rows m (raw fp32)
    const float* B = g_scratch + (size_t)t * 512 * 256;    // rows e (RN tf32)
    float* C = out + (size_t)t * 512 * 512;

    const uint32_t aoff[2] = {sb, sb + S2_STAGE};
    const uint32_t boff[2] = {sb + S2_A, sb + S2_STAGE + S2_A};

    // A: 2048 float4, B: 1024 float4; 512 threads
    auto cpasync_tile = [&](int kt, int buf) {
#pragma unroll
        for (int i = 0; i < 4; ++i) {
            const int idx = tid + i * 512;
            const int row = idx >> 3, ch = idx & 7;        // row 0..255
            CP_ASYNC16(aoff[buf] + row * 144 + ch * 16,
                       A + (size_t)(m0 + row) * 256 + kt * 32 + ch * 4);
        }
#pragma unroll
        for (int i = 0; i < 2; ++i) {
            const int idx = tid + i * 512;
            const int row = idx >> 3, ch = idx & 7;        // row 0..127
            CP_ASYNC16(boff[buf] + row * 144 + ch * 16,
                       B + (size_t)(n0 + row) * 256 + kt * 32 + ch * 4);
        }
    };

    const uint32_t a_lane = (uint32_t)(((((lid >> 3) & 1) * 8) + (lid & 7)) * 144
                                       + ((lid >> 4) & 1) * 16);
    const uint32_t b_lane = (uint32_t)(((((lid >> 4) & 1) * 8) + (lid & 7)) * 144
                                       + ((lid >> 3) & 1) * 16);

    float acc[4][4][4];
#pragma unroll
    for (int mi = 0; mi < 4; ++mi)
#pragma unroll
        for (int nj = 0; nj < 4; ++nj)
#pragma unroll
            for (int q = 0; q < 4; ++q) acc[mi][nj][q] = 0.0f;

    auto compute_tile = [&](int buf) {
        const uint32_t ab = aoff[buf] + a_lane + warp_m * 144;
        const uint32_t bb = boff[buf] + b_lane + warp_n * 144;
#pragma unroll
        for (int ks = 0; ks < 4; ++ks) {
            uint32_t af[4][4], bf[4][2];
#pragma unroll
            for (int mi = 0; mi < 4; ++mi)
                LDSM4(af[mi][0], af[mi][1], af[mi][2], af[mi][3],
                      ab + mi * (16 * 144) + ks * 32);
#pragma unroll
            for (int p = 0; p < 2; ++p)
                LDSM4(bf[2 * p][0], bf[2 * p][1], bf[2 * p + 1][0], bf[2 * p + 1][1],
                      bb + p * (16 * 144) + ks * 32);
#pragma unroll
            for (int mi = 0; mi < 4; ++mi)
#pragma unroll
                for (int nj = 0; nj < 4; ++nj)
                    mma_tf32(acc[mi][nj], af[mi][0], af[mi][1], af[mi][2], af[mi][3],
                             bf[nj][0], bf[nj][1]);
        }
    };

    cpasync_tile(0, 0);
    CP_COMMIT();
    int buf = 0;
#pragma unroll 1
    for (int kt = 0; kt < 8; ++kt) {
        if (kt < 7) {
            cpasync_tile(kt + 1, buf ^ 1);
            CP_COMMIT();
            CP_WAIT1();
        } else {
            CP_WAIT0();
        }
        __syncthreads();
        compute_tile(buf);
        if (kt < 7) __syncthreads();
        buf ^= 1;
    }

#pragma unroll
    for (int mi = 0; mi < 4; ++mi) {
        const int r0 = m0 + warp_m + 16 * mi + g;
        const int r1 = r0 + 8;
#pragma unroll
        for (int nj = 0; nj < 4; ++nj) {
            const int col = n0 + warp_n + 8 * nj + 2 * tg;
            float2 v0, v1;
            v0.x = acc[mi][nj][0]; v0.y = acc[mi][nj][1];
            v1.x = acc[mi][nj][2]; v1.y = acc[mi][nj][3];
            *reinterpret_cast<float2*>(C + (size_t)r0 * 512 + col) = v0;
            *reinterpret_cast<float2*>(C + (size_t)r1 * 512 + col) = v1;
        }
    }
}

extern "C" void kernel_launch(void* const* d_in, const int* in_sizes, int n_in,
                              void* d_out, int out_size) {
    const float* x_main = (const float*)d_in[0];  // [1,128,512,256]
    const float* x_aux  = (const float*)d_in[1];  // [256,128,256]
    const float* W      = (const float*)d_in[2];  // [256,512]
    const float* b      = (const float*)d_in[3];  // [512]
    float* out = (float*)d_out;                   // [128,512,512]

    cudaFuncSetAttribute(slam_stage1,
                         cudaFuncAttributeMaxDynamicSharedMemorySize, SMEM_S1);
    cudaFuncSetAttribute(slam_stage2,
                         cudaFuncAttributeMaxDynamicSharedMemorySize, SMEM_S2);

    // W -> Wt (tf32-rounded transpose), once per launch
    w_transpose_kernel<<<dim3(8, 16), dim3(32, 32)>>>(W);
    // Stage 1: per-t  D[e(512) x k(256)] = Wt . x_aux[.,t,.]^T (+bias, relu) -> scratch
    slam_stage1<<<dim3(2, 4, 128), 256, SMEM_S1>>>(x_aux, b);
    // Stage 2: per-t  D[m(512) x e(512)] = x_main[t] . scratch[t]^T -> out
    slam_stage2<<<dim3(4, 2, 128), 512, SMEM_S2>>>(x_main, out);
}

// round 15
// speedup vs baseline: 1.0823x; 1.0823x over previous
#include <cuda_runtime.h>
#include <cstdint>

// Shapes (fixed):
//   x_main: [1, T=128, M=512, K=256] fp32
//   x_aux : [K=256, T=128, Da=256]   fp32
//   W     : [Da=256, E=512]          fp32
//   b     : [E=512]                  fp32
//   out   : [1,T,M,E,1] = [128,512,512] fp32
//
// R11 (best verified: 168.7us, rel_err 5.49e-4) with both k-tile mainloops
// FULLY UNROLLED: all buffer selects / kt-scaled addresses become immediates,
// cutting the ALU-pipe issue share (16% in the R10 fused profile) and
// shortening the post-barrier ramp.  Everything else byte-identical to R11.
//
// Stage 1 (per t): scratch[t][e][k] = relu( sum_d Wt[e][d]*x_aux[k][t][d] + b[e] )
//   A = Wt rows e (cp.async, RN tf32), B = x_aux rows k (LDG + cvt.rna + STS).
// Stage 2 (per t): out[t][m][e] = sum_k x_main[t][m][k]*scratch[t][e][k]
//   A = raw fp32 x_main (HW RZ-truncated by MMA), B = scratch (RN tf32),
//   both cp.async.

__device__ __align__(16) float g_scratch[128 * 512 * 256];  // [T][E][K], 64 MB
__device__ __align__(16) float g_Wt[512 * 256];             // W^T, tf32-rounded

static constexpr int S_A = 18432;       // 128 rows x 36 floats (144 B rows)
static constexpr int S_B = 18432;
static constexpr int SMEM_TOTAL = 2 * (S_A + S_B);   // 73728 -> 2 CTAs/SM

__device__ __forceinline__ uint32_t smem_u32(const void* p) {
    uint32_t a;
    asm("{ .reg .u64 t; cvta.to.shared.u64 t, %1; cvt.u32.u64 %0, t; }" : "=r"(a) : "l"(p));
    return a;
}
__device__ __forceinline__ float f2tf32f(float f) {
    uint32_t r;
    asm("cvt.rna.tf32.f32 %0, %1;" : "=r"(r) : "f"(f));
    return __uint_as_float(r);
}
#define CP_ASYNC16(dst32, src) \
    asm volatile("cp.async.cg.shared.global [%0], [%1], 16;" :: "r"(dst32), "l"(src))
#define CP_COMMIT() asm volatile("cp.async.commit_group;" ::: "memory")
#define CP_WAIT0()  asm volatile("cp.async.wait_group 0;" ::: "memory")
#define CP_WAIT1()  asm volatile("cp.async.wait_group 1;" ::: "memory")
#define STS128(addr, v) \
    asm volatile("st.shared.v4.b32 [%0], {%1,%2,%3,%4};" \
                 :: "r"(addr), "f"(v.x), "f"(v.y), "f"(v.z), "f"(v.w) : "memory")
#define LDSM4(r0, r1, r2, r3, addr) \
    asm volatile("ldmatrix.sync.aligned.m8n8.x4.shared.b16 {%0,%1,%2,%3}, [%4];" \
                 : "=r"(r0), "=r"(r1), "=r"(r2), "=r"(r3) : "r"(addr))

__device__ __forceinline__ void mma_tf32(float* d, uint32_t a0, uint32_t a1,
                                         uint32_t a2, uint32_t a3,
                                         uint32_t b0, uint32_t b1) {
    asm volatile(
        "mma.sync.aligned.m16n8k8.row.col.f32.tf32.tf32.f32 "
        "{%0,%1,%2,%3}, {%4,%5,%6,%7}, {%8,%9}, {%0,%1,%2,%3};"
        : "+f"(d[0]), "+f"(d[1]), "+f"(d[2]), "+f"(d[3])
        : "r"(a0), "r"(a1), "r"(a2), "r"(a3), "r"(b0), "r"(b1));
}

// Pre-pass: Wt[e][d] = rna_tf32(W[d][e]).  32x32 smem-tiled transpose.
__global__ void w_transpose_kernel(const float* __restrict__ W) {
    __shared__ float s[32][33];
    const int d0 = blockIdx.x * 32, e0 = blockIdx.y * 32;
    const int tx = threadIdx.x, ty = threadIdx.y;
    s[ty][tx] = W[(size_t)(d0 + ty) * 512 + e0 + tx];
    __syncthreads();
    g_Wt[(size_t)(e0 + ty) * 256 + d0 + tx] = f2tf32f(s[tx][ty]);
}

// ============================ Stage 1 ============================
__global__ void __launch_bounds__(256, 2)
slam_stage1(const float* __restrict__ x_aux, const float* __restrict__ bias) {
    extern __shared__ __align__(16) char smem[];
    const uint32_t sb = smem_u32(smem);
    const int tid = threadIdx.x, wid = tid >> 5, lid = tid & 31;
    const int g = lid >> 2, tg = lid & 3;
    const int warp_m = (wid & 1) * 64;
    const int warp_n = (wid >> 1) * 32;
    const int t = blockIdx.z, m0 = blockIdx.y * 128, n0 = blockIdx.x * 128;

    const float* ld_src = x_aux + (size_t)t * 256;      // rows k, stride 32768
    float* C = g_scratch + (size_t)t * 512 * 256;       // [e][k]

    const uint32_t aoff[2] = {sb, sb + S_A};
    const uint32_t boff[2] = {sb + 2 * S_A, sb + 2 * S_A + S_B};

    auto cpasync_tile = [&](int kt, int buf) {
#pragma unroll
        for (int i = 0; i < 4; ++i) {
            const int idx = tid + i * 256;
            const int row = idx >> 3, ch = idx & 7;
            CP_ASYNC16(aoff[buf] + row * 144 + ch * 16,
                       g_Wt + (size_t)(m0 + row) * 256 + kt * 32 + ch * 4);
        }
    };
    const int srow = tid >> 3, sch = tid & 7;
    auto ldg_tile = [&](int kt, float4 (&r)[4]) {
#pragma unroll
        for (int i = 0; i < 4; ++i)
            r[i] = *reinterpret_cast<const float4*>(
                ld_src + (size_t)(n0 + srow + i * 32) * (128 * 256) + kt * 32 + sch * 4);
    };
    auto sts_tile = [&](float4 (&r)[4], int buf) {
        const uint32_t base = boff[buf] + srow * 144 + sch * 16;
#pragma unroll
        for (int i = 0; i < 4; ++i) {
            float4 v = r[i];
            v.x = f2tf32f(v.x); v.y = f2tf32f(v.y);
            v.z = f2tf32f(v.z); v.w = f2tf32f(v.w);
            STS128(base + i * 32 * 144, v);
        }
    };

    const uint32_t a_lane = (uint32_t)(((((lid >> 3) & 1) * 8) + (lid & 7)) * 144
                                       + ((lid >> 4) & 1) * 16);
    const uint32_t b_lane = (uint32_t)(((((lid >> 4) & 1) * 8) + (lid & 7)) * 144
                                       + ((lid >> 3) & 1) * 16);

    float acc[4][4][4];
#pragma unroll
    for (int mi = 0; mi < 4; ++mi)
#pragma unroll
        for (int nj = 0; nj < 4; ++nj)
#pragma unroll
            for (int q = 0; q < 4; ++q) acc[mi][nj][q] = 0.0f;

    auto compute_tile = [&](int buf) {
        const uint32_t ab = aoff[buf] + a_lane + warp_m * 144;
        const uint32_t bb = boff[buf] + b_lane + warp_n * 144;
#pragma unroll
        for (int ks = 0; ks < 4; ++ks) {
            uint32_t af[4][4], bf[4][2];
#pragma unroll
            for (int mi = 0; mi < 4; ++mi)
                LDSM4(af[mi][0], af[mi][1], af[mi][2], af[mi][3],
                      ab + mi * (16 * 144) + ks * 32);
#pragma unroll
            for (int p = 0; p < 2; ++p)
                LDSM4(bf[2 * p][0], bf[2 * p][1], bf[2 * p + 1][0], bf[2 * p + 1][1],
                      bb + p * (16 * 144) + ks * 32);
#pragma unroll
            for (int mi = 0; mi < 4; ++mi)
#pragma unroll
                for (int nj = 0; nj < 4; ++nj)
                    mma_tf32(acc[mi][nj], af[mi][0], af[mi][1], af[mi][2], af[mi][3],
                             bf[nj][0], bf[nj][1]);
        }
    };

    float4 stage_regs[4];
    cpasync_tile(0, 0);
    CP_COMMIT();
    ldg_tile(0, stage_regs);
    CP_WAIT0();
    sts_tile(stage_regs, 0);
    __syncthreads();

    // fully unrolled mainloop: buffer indices and kt offsets are immediates
#pragma unroll
    for (int kt = 0; kt < 8; ++kt) {
        const int buf = kt & 1;
        if (kt < 7) {
            cpasync_tile(kt + 1, buf ^ 1);
            CP_COMMIT();
            ldg_tile(kt + 1, stage_regs);
        }
        compute_tile(buf);
        if (kt < 7) {
            CP_WAIT0();
            sts_tile(stage_regs, buf ^ 1);
            __syncthreads();
        }
    }

#pragma unroll
    for (int mi = 0; mi < 4; ++mi) {
        const int r0 = m0 + warp_m + 16 * mi + g;
        const int r1 = r0 + 8;
        const float bv0 = bias[r0], bv1 = bias[r1];
#pragma unroll
        for (int nj = 0; nj < 4; ++nj) {
            const int col = n0 + warp_n + 8 * nj + 2 * tg;
            float2 v0, v1;
            v0.x = f2tf32f(fmaxf(acc[mi][nj][0] + bv0, 0.0f));
            v0.y = f2tf32f(fmaxf(acc[mi][nj][1] + bv0, 0.0f));
            v1.x = f2tf32f(fmaxf(acc[mi][nj][2] + bv1, 0.0f));
            v1.y = f2tf32f(fmaxf(acc[mi][nj][3] + bv1, 0.0f));
            *reinterpret_cast<float2*>(C + (size_t)r0 * 256 + col) = v0;
            *reinterpret_cast<float2*>(C + (size_t)r1 * 256 + col) = v1;
        }
    }
}

// ============================ Stage 2 ============================
__global__ void __launch_bounds__(256, 2)
slam_stage2(const float* __restrict__ x_main, float* __restrict__ out) {
    extern __shared__ __align__(16) char smem[];
    const uint32_t sb = smem_u32(smem);
    const int tid = threadIdx.x, wid = tid >> 5, lid = tid & 31;
    const int g = lid >> 2, tg = lid & 3;
    const int warp_m = (wid & 1) * 64;
    const int warp_n = (wid >> 1) * 32;
    const int t = blockIdx.z, m0 = blockIdx.y * 128, n0 = blockIdx.x * 128;

    const float* A = x_main + (size_t)t * 512 * 256;       // rows m (raw fp32)
    const float* B = g_scratch + (size_t)t * 512 * 256;    // rows e (RN tf32)
    float* C = out + (size_t)t * 512 * 512;

    const uint32_t aoff[2] = {sb, sb + S_A};
    const uint32_t boff[2] = {sb + 2 * S_A, sb + 2 * S_A + S_B};

    auto cpasync_tile = [&](int kt, int buf) {
#pragma unroll
        for (int i = 0; i < 4; ++i) {
            const int idx = tid + i * 256;
            const int row = idx >> 3, ch = idx & 7;
            CP_ASYNC16(aoff[buf] + row * 144 + ch * 16,
                       A + (size_t)(m0 + row) * 256 + kt * 32 + ch * 4);
        }
#pragma unroll
        for (int i = 0; i < 4; ++i) {
            const int idx = tid + i * 256;
            const int row = idx >> 3, ch = idx & 7;
            CP_ASYNC16(boff[buf] + row * 144 + ch * 16,
                       B + (size_t)(n0 + row) * 256 + kt * 32 + ch * 4);
        }
    };

    const uint32_t a_lane = (uint32_t)(((((lid >> 3) & 1) * 8) + (lid & 7)) * 144
                                       + ((lid >> 4) & 1) * 16);
    const uint32_t b_lane = (uint32_t)(((((lid >> 4) & 1) * 8) + (lid & 7)) * 144
                                       + ((lid >> 3) & 1) * 16);

    float acc[4][4][4];
#pragma unroll
    for (int mi = 0; mi < 4; ++mi)
#pragma unroll
        for (int nj = 0; nj < 4; ++nj)
#pragma unroll
            for (int q = 0; q < 4; ++q) acc[mi][nj][q] = 0.0f;

    auto compute_tile = [&](int buf) {
        const uint32_t ab = aoff[buf] + a_lane + warp_m * 144;
        const uint32_t bb = boff[buf] + b_lane + warp_n * 144;
#pragma unroll
        for (int ks = 0; ks < 4; ++ks) {
            uint32_t af[4][4], bf[4][2];
#pragma unroll
            for (int mi = 0; mi < 4; ++mi)
                LDSM4(af[mi][0], af[mi][1], af[mi][2], af[mi][3],
                      ab + mi * (16 * 144) + ks * 32);
#pragma unroll
            for (int p = 0; p < 2; ++p)
                LDSM4(bf[2 * p][0], bf[2 * p][1], bf[2 * p + 1][0], bf[2 * p + 1][1],
                      bb + p * (16 * 144) + ks * 32);
#pragma unroll
            for (int mi = 0; mi < 4; ++mi)
#pragma unroll
                for (int nj = 0; nj < 4; ++nj)
                    mma_tf32(acc[mi][nj], af[mi][0], af[mi][1], af[mi][2], af[mi][3],
                             bf[nj][0], bf[nj][1]);
        }
    };

    cpasync_tile(0, 0);
    CP_COMMIT();
    // fully unrolled mainloop
#pragma unroll
    for (int kt = 0; kt < 8; ++kt) {
        const int buf = kt & 1;
        if (kt < 7) {
            cpasync_tile(kt + 1, buf ^ 1);
            CP_COMMIT();
            CP_WAIT1();
        } else {
            CP_WAIT0();
        }
        __syncthreads();
        compute_tile(buf);
        if (kt < 7) __syncthreads();
    }

#pragma unroll
    for (int mi = 0; mi < 4; ++mi) {
        const int r0 = m0 + warp_m + 16 * mi + g;
        const int r1 = r0 + 8;
#pragma unroll
        for (int nj = 0; nj < 4; ++nj) {
            const int col = n0 + warp_n + 8 * nj + 2 * tg;
            float2 v0, v1;
            v0.x = acc[mi][nj][0]; v0.y = acc[mi][nj][1];
            v1.x = acc[mi][nj][2]; v1.y = acc[mi][nj][3];
            *reinterpret_cast<float2*>(C + (size_t)r0 * 512 + col) = v0;
            *reinterpret_cast<float2*>(C + (size_t)r1 * 512 + col) = v1;
        }
    }
}

extern "C" void kernel_launch(void* const* d_in, const int* in_sizes, int n_in,
                              void* d_out, int out_size) {
    const float* x_main = (const float*)d_in[0];  // [1,128,512,256]
    const float* x_aux  = (const float*)d_in[1];  // [256,128,256]
    const float* W      = (const float*)d_in[2];  // [256,512]
    const float* b      = (const float*)d_in[3];  // [512]
    float* out = (float*)d_out;                   // [128,512,512]

    cudaFuncSetAttribute(slam_stage1,
                         cudaFuncAttributeMaxDynamicSharedMemorySize, SMEM_TOTAL);
    cudaFuncSetAttribute(slam_stage2,
                         cudaFuncAttributeMaxDynamicSharedMemorySize, SMEM_TOTAL);

    // W -> Wt (tf32-rounded transpose), once per launch
    w_transpose_kernel<<<dim3(8, 16), dim3(32, 32)>>>(W);
    // Stage 1: per-t  D[e(512) x k(256)] = Wt . x_aux[.,t,.]^T (+bias, relu) -> scratch
    slam_stage1<<<dim3(2, 4, 128), 256, SMEM_TOTAL>>>(x_aux, b);
    // Stage 2: per-t  D[m(512) x e(512)] = x_main[t] . scratch[t]^T -> out
    slam_stage2<<<dim3(4, 4, 128), 256, SMEM_TOTAL>>>(x_main, out);
}